// round 5
// baseline (speedup 1.0000x reference)
#include <cuda_runtime.h>
#include <cuda_fp16.h>
#include <math.h>
#include <stdint.h>

#define C_FULL 1024
#define C_HALF 512
#define HW     4096
#define KLOG   2048

// ---------------- scratch (device globals; no runtime allocation) ----------
__device__ __half g_xTm_h[HW*C_FULL], g_xTm_l[HW*C_FULL];
__device__ __half g_xTf_h[HW*C_FULL], g_xTf_l[HW*C_FULL];
__device__ __half g_xTl_h[HW*C_FULL], g_xTl_l[HW*C_FULL];
__device__ __half g_Wq_h [C_HALF*C_FULL], g_Wq_l [C_HALF*C_FULL];
__device__ __half g_Wk1_h[C_HALF*C_FULL], g_Wk1_l[C_HALF*C_FULL];
__device__ __half g_Wk2_h[C_HALF*C_FULL], g_Wk2_l[C_HALF*C_FULL];
__device__ __half g_Wv_h [C_FULL*C_FULL];                 // lo of Wv unused
__device__ __half g_q_h [C_HALF*HW], g_q_l [C_HALF*HW];
__device__ __half g_kf_h[C_HALF*HW], g_kf_l[C_HALF*HW];
__device__ __half g_kl_h[C_HALF*HW], g_kl_l[C_HALF*HW];
__device__ __half g_vT_h[HW*C_FULL];                      // lo of V unused
__device__ float  g_lf[C_FULL*C_FULL], g_ll[C_FULL*C_FULL];
__device__ __half g_S_h[C_FULL*C_FULL], g_S_l[C_FULL*C_FULL];

// ---------------- helpers ---------------------------------------------------
__device__ __forceinline__ uint32_t smem_u32(const void* p) {
    uint32_t r;
    asm("{ .reg .u64 t; cvta.to.shared.u64 t, %1; cvt.u32.u64 %0, t; }"
        : "=r"(r) : "l"(p));
    return r;
}
__device__ __forceinline__ void cp_async16(uint32_t dst, const void* src) {
    asm volatile("cp.async.cg.shared.global [%0], [%1], 16;" :: "r"(dst), "l"(src));
}
__device__ __forceinline__ void cp_commit() { asm volatile("cp.async.commit_group;"); }

__device__ __forceinline__ void ldsm4(uint32_t addr, uint32_t& r0, uint32_t& r1,
                                      uint32_t& r2, uint32_t& r3) {
    asm volatile("ldmatrix.sync.aligned.m8n8.x4.shared.b16 {%0,%1,%2,%3}, [%4];"
                 : "=r"(r0), "=r"(r1), "=r"(r2), "=r"(r3) : "r"(addr));
}
__device__ __forceinline__ void hmma(float* d, const uint32_t* a, const uint32_t* b) {
    asm volatile("mma.sync.aligned.m16n8k16.row.col.f32.f16.f16.f32 "
                 "{%0,%1,%2,%3}, {%4,%5,%6,%7}, {%8,%9}, {%0,%1,%2,%3};"
                 : "+f"(d[0]), "+f"(d[1]), "+f"(d[2]), "+f"(d[3])
                 : "r"(a[0]), "r"(a[1]), "r"(a[2]), "r"(a[3]),
                   "r"(b[0]), "r"(b[1]));
}

// ---------------- unified multi-job GEMM ------------------------------------
// D = A[M,K] @ B[N,K]^T, fp16-split operands, fp32 accum.
// tm bit0: add A_h*B_l term; tm bit1: add A_l*B_h term (A_h*B_h always).
// mode 0: split-store D+bias[m] -> Ch/Cl        (convs q/kf/kl)
// mode 1: hi-store   D+bias[n] -> Ch            (conv vT)
// mode 2: fp32 store D -> Cf                    (logits)
// mode 3: fp32 store gamma*D + 0.5*(xf+xl)->Cf  (final)
struct Jobs {
    const __half* Ah[4]; const __half* Al[4];
    const __half* Bh[4]; const __half* Bl[4];
    __half* Ch[4]; __half* Cl[4]; float* Cf[4];
    const float* bias[4];
    const float* xf; const float* xl; const float* gpt;
    int N[4], K[4], gx[4], tm[4], mode[4], blk0[4];
    int njobs;
};

#define BM 128
#define BN 128
#define BK 32
#define TSTRIDE 40
#define TILE_BYTES (128 * TSTRIDE * 2)       // 10240
#define STAGE_BYTES (4 * TILE_BYTES)         // 40960
#define GEMM_SMEM (3 * STAGE_BYTES)          // 122880

__global__ __launch_bounds__(256, 1)
void mma_gemm(Jobs P)
{
    extern __shared__ __half sm[];
    // job resolution
    int j = 0;
    #pragma unroll
    for (int t = 1; t < 4; t++)
        if (t < P.njobs && (int)blockIdx.x >= P.blk0[t]) j = t;
    const int rel = blockIdx.x - P.blk0[j];
    const int bx = rel % P.gx[j], by = rel / P.gx[j];

    const __half* __restrict__ Ah = P.Ah[j];
    const __half* __restrict__ Al = P.Al[j];
    const __half* __restrict__ Bh = P.Bh[j];
    const __half* __restrict__ Bl = P.Bl[j];
    const int N = P.N[j], K = P.K[j], tm = P.tm[j], mode = P.mode[j];

    const int tid  = threadIdx.x;
    const int lane = tid & 31, wid = tid >> 5;
    const int warp_m = wid & 3, warp_n = wid >> 2;       // 4 x 2 warps
    const int bm0 = by * BM, bn0 = bx * BN;
    const uint32_t su = smem_u32(sm);

    float acc[2][8][4];
    #pragma unroll
    for (int i = 0; i < 2; i++)
        #pragma unroll
        for (int q = 0; q < 8; q++)
            #pragma unroll
            for (int k = 0; k < 4; k++) acc[i][q][k] = 0.0f;

#define LOAD_STAGE(s, kt) do {                                                \
    const uint32_t sbase_ = su + (uint32_t)(s) * STAGE_BYTES;                 \
    const size_t acol_ = (size_t)(kt) * BK;                                   \
    _Pragma("unroll")                                                         \
    for (int it_ = 0; it_ < 2; it_++) {                                       \
        const int c_ = tid + it_ * 256;                                       \
        const int row_ = c_ >> 2;                                             \
        const int kc_ = (c_ & 3) * 8;                                         \
        const uint32_t off_ = (uint32_t)(row_ * TSTRIDE + kc_) * 2;           \
        const size_t ga_ = (size_t)(bm0 + row_) * K + acol_ + kc_;            \
        const size_t gb_ = (size_t)(bn0 + row_) * K + acol_ + kc_;            \
        cp_async16(sbase_ + 0 * TILE_BYTES + off_, Ah + ga_);                 \
        cp_async16(sbase_ + 2 * TILE_BYTES + off_, Bh + gb_);                 \
        if (tm & 2) cp_async16(sbase_ + 1 * TILE_BYTES + off_, Al + ga_);     \
        if (tm & 1) cp_async16(sbase_ + 3 * TILE_BYTES + off_, Bl + gb_);     \
    }                                                                         \
    cp_commit();                                                              \
} while (0)

    const int NT = K / BK;
    LOAD_STAGE(0, 0);
    LOAD_STAGE(1, 1);

    for (int kt = 0; kt < NT; kt++) {
        if (kt + 2 < NT) {
            LOAD_STAGE((kt + 2) % 3, kt + 2);
            asm volatile("cp.async.wait_group 2;" ::: "memory");
        } else if (kt + 1 < NT) {
            asm volatile("cp.async.wait_group 1;" ::: "memory");
        } else {
            asm volatile("cp.async.wait_group 0;" ::: "memory");
        }
        __syncthreads();

        const uint32_t sbase = su + (uint32_t)(kt % 3) * STAGE_BYTES;
        #pragma unroll
        for (int ks = 0; ks < 2; ks++) {
            uint32_t ah[2][4], al[2][4], bh[8][2], bl[8][2];
            #pragma unroll
            for (int i = 0; i < 2; i++) {
                const int r   = warp_m * 32 + i * 16 + (lane & 15);
                const int col = ks * 16 + (lane >> 4) * 8;
                const uint32_t ad = sbase + (uint32_t)(r * TSTRIDE + col) * 2;
                ldsm4(ad, ah[i][0], ah[i][1], ah[i][2], ah[i][3]);
                if (tm & 2)
                    ldsm4(ad + TILE_BYTES, al[i][0], al[i][1], al[i][2], al[i][3]);
            }
            #pragma unroll
            for (int p = 0; p < 4; p++) {
                const int g  = lane >> 3, i8 = lane & 7;
                const int n   = warp_n * 64 + p * 16 + ((g >> 1) << 3) + i8;
                const int col = ks * 16 + (g & 1) * 8;
                const uint32_t bd = sbase + 2 * TILE_BYTES +
                                    (uint32_t)(n * TSTRIDE + col) * 2;
                ldsm4(bd, bh[2*p][0], bh[2*p][1], bh[2*p+1][0], bh[2*p+1][1]);
                if (tm & 1)
                    ldsm4(bd + TILE_BYTES, bl[2*p][0], bl[2*p][1], bl[2*p+1][0], bl[2*p+1][1]);
            }
            #pragma unroll
            for (int i = 0; i < 2; i++)
                #pragma unroll
                for (int q = 0; q < 8; q++)
                    hmma(acc[i][q], ah[i], bh[q]);
            if (tm & 2) {
                #pragma unroll
                for (int i = 0; i < 2; i++)
                    #pragma unroll
                    for (int q = 0; q < 8; q++)
                        hmma(acc[i][q], al[i], bh[q]);
            }
            if (tm & 1) {
                #pragma unroll
                for (int i = 0; i < 2; i++)
                    #pragma unroll
                    for (int q = 0; q < 8; q++)
                        hmma(acc[i][q], ah[i], bl[q]);
            }
        }
        __syncthreads();
    }
#undef LOAD_STAGE

    // ---- epilogue ----
    const int tq = lane >> 2, tr = lane & 3;
    const float gam = (mode == 3) ? P.gpt[0] : 0.0f;
    #pragma unroll
    for (int i = 0; i < 2; i++) {
        #pragma unroll
        for (int h2 = 0; h2 < 2; h2++) {
            const int row = bm0 + warp_m * 32 + i * 16 + tq + h2 * 8;
            const float bm_ = (mode == 0) ? P.bias[j][row] : 0.0f;
            #pragma unroll
            for (int q = 0; q < 8; q++) {
                const int col = bn0 + warp_n * 64 + q * 8 + tr * 2;
                float v0 = acc[i][q][h2 * 2 + 0];
                float v1 = acc[i][q][h2 * 2 + 1];
                const size_t idx = (size_t)row * N + col;
                if (mode == 0) {
                    v0 += bm_; v1 += bm_;
                    const __half h0 = __float2half_rn(v0);
                    const __half h1 = __float2half_rn(v1);
                    *reinterpret_cast<__half2*>(P.Ch[j] + idx) = __halves2half2(h0, h1);
                    *reinterpret_cast<__half2*>(P.Cl[j] + idx) =
                        __halves2half2(__float2half_rn(v0 - __half2float(h0)),
                                       __float2half_rn(v1 - __half2float(h1)));
                } else if (mode == 1) {
                    v0 += P.bias[j][col]; v1 += P.bias[j][col + 1];
                    *reinterpret_cast<__half2*>(P.Ch[j] + idx) =
                        __halves2half2(__float2half_rn(v0), __float2half_rn(v1));
                } else if (mode == 2) {
                    *reinterpret_cast<float2*>(P.Cf[j] + idx) = make_float2(v0, v1);
                } else {
                    const float2 a2 = *reinterpret_cast<const float2*>(P.xf + idx);
                    const float2 b2 = *reinterpret_cast<const float2*>(P.xl + idx);
                    *reinterpret_cast<float2*>(P.Cf[j] + idx) =
                        make_float2(gam * v0 + 0.5f * (a2.x + b2.x),
                                    gam * v1 + 0.5f * (a2.y + b2.y));
                }
            }
        }
    }
}

// ---------------- batched transpose + fp16 split ----------------------------
struct TJobs { const float* x[3]; __half* th[3]; __half* tl[3]; };
__global__ __launch_bounds__(256)
void transpose_split(TJobs T)
{
    __shared__ float t[32][33];
    const int z = blockIdx.z;
    const float* __restrict__ x = T.x[z];
    __half* __restrict__ th = T.th[z];
    __half* __restrict__ tl = T.tl[z];
    const int tx = threadIdx.x & 31, ty = threadIdx.x >> 5;
    const int c0 = blockIdx.x * 32;
    const int r0 = blockIdx.y * 32;
    #pragma unroll
    for (int i = 0; i < 4; i++)
        t[ty + i * 8][tx] = x[(size_t)(r0 + ty + i * 8) * HW + c0 + tx];
    __syncthreads();
    #pragma unroll
    for (int i = 0; i < 4; i++) {
        const float v = t[tx][ty + i * 8];
        const size_t idx = (size_t)(c0 + ty + i * 8) * C_FULL + r0 + tx;
        const __half h = __float2half_rn(v);
        th[idx] = h;
        tl[idx] = __float2half_rn(v - __half2float(h));
    }
}

// ---------------- merged weight splits (lo optional) ------------------------
struct SJobs { const float* x[4]; __half* h[4]; __half* l[4]; int end[4]; };
__global__ __launch_bounds__(256)
void split4_kernel(SJobs S)
{
    int i = blockIdx.x * 256 + threadIdx.x;
    int j = 0;
    #pragma unroll
    for (int t = 1; t < 4; t++) if (i >= S.end[t - 1]) j = t;
    const int base = (j == 0) ? 0 : S.end[j - 1];
    if (i >= S.end[3]) return;
    const int k = i - base;
    const float v = S.x[j][k];
    const __half hh = __float2half_rn(v);
    S.h[j][k] = hh;
    if (S.l[j]) S.l[j][k] = __float2half_rn(v - __half2float(hh));
}

// ---------------- fused dual softmax, split-fp16 output ---------------------
__global__ __launch_bounds__(256)
void softmax_sum_kernel(const float* __restrict__ LF, const float* __restrict__ LL,
                        __half* __restrict__ Sh, __half* __restrict__ Sl)
{
    const int row = blockIdx.x;
    const int tid = threadIdx.x;
    __shared__ float red[256];

    const float* pf = LF + (size_t)row * 1024;
    const float* pl = LL + (size_t)row * 1024;

    float vf[4], vl[4];
    #pragma unroll
    for (int k = 0; k < 4; k++) { vf[k] = pf[tid + 256 * k]; vl[k] = pl[tid + 256 * k]; }

    float m = fmaxf(fmaxf(vf[0], vf[1]), fmaxf(vf[2], vf[3]));
    red[tid] = m; __syncthreads();
    for (int s = 128; s > 0; s >>= 1) { if (tid < s) red[tid] = fmaxf(red[tid], red[tid + s]); __syncthreads(); }
    const float Mf = red[0]; __syncthreads();

    float ef[4], sf = 0.0f;
    #pragma unroll
    for (int k = 0; k < 4; k++) { ef[k] = expf(vf[k] - Mf); sf += ef[k]; }
    red[tid] = sf; __syncthreads();
    for (int s = 128; s > 0; s >>= 1) { if (tid < s) red[tid] += red[tid + s]; __syncthreads(); }
    const float Sf = red[0]; __syncthreads();

    m = fmaxf(fmaxf(vl[0], vl[1]), fmaxf(vl[2], vl[3]));
    red[tid] = m; __syncthreads();
    for (int s = 128; s > 0; s >>= 1) { if (tid < s) red[tid] = fmaxf(red[tid], red[tid + s]); __syncthreads(); }
    const float Ml = red[0]; __syncthreads();

    float el[4], sl = 0.0f;
    #pragma unroll
    for (int k = 0; k < 4; k++) { el[k] = expf(vl[k] - Ml); sl += el[k]; }
    red[tid] = sl; __syncthreads();
    for (int s = 128; s > 0; s >>= 1) { if (tid < s) red[tid] += red[tid + s]; __syncthreads(); }
    const float Sl_ = red[0];

    const float invf = 1.0f / Sf, invl = 1.0f / Sl_;
    #pragma unroll
    for (int k = 0; k < 4; k++) {
        const float v = ef[k] * invf + el[k] * invl;
        const size_t idx = (size_t)row * 1024 + tid + 256 * k;
        const __half h = __float2half_rn(v);
        Sh[idx] = h;
        Sl[idx] = __float2half_rn(v - __half2float(h));
    }
}

// ---------------------------------------------------------------------------
extern "C" void kernel_launch(void* const* d_in, const int* in_sizes, int n_in,
                              void* d_out, int out_size)
{
    (void)in_sizes; (void)n_in; (void)out_size;
    const float* x_f   = (const float*)d_in[0];
    const float* x_m   = (const float*)d_in[1];
    const float* x_l   = (const float*)d_in[2];
    const float* Wq    = (const float*)d_in[3];
    const float* bq    = (const float*)d_in[4];
    const float* Wk1   = (const float*)d_in[5];
    const float* bk1   = (const float*)d_in[6];
    const float* Wk2   = (const float*)d_in[7];
    const float* bk2   = (const float*)d_in[8];
    const float* Wv    = (const float*)d_in[9];
    const float* bv    = (const float*)d_in[10];
    const float* gamma = (const float*)d_in[11];
    float* out = (float*)d_out;

    __half *xTm_h, *xTm_l, *xTf_h, *xTf_l, *xTl_h, *xTl_l;
    __half *wq_h, *wq_l, *wk1_h, *wk1_l, *wk2_h, *wk2_l, *wv_h;
    __half *q_h, *q_l, *kf_h, *kf_l, *kl_h, *kl_l, *vT_h, *s_h, *s_l;
    float *lf, *ll;
    cudaGetSymbolAddress((void**)&xTm_h, g_xTm_h); cudaGetSymbolAddress((void**)&xTm_l, g_xTm_l);
    cudaGetSymbolAddress((void**)&xTf_h, g_xTf_h); cudaGetSymbolAddress((void**)&xTf_l, g_xTf_l);
    cudaGetSymbolAddress((void**)&xTl_h, g_xTl_h); cudaGetSymbolAddress((void**)&xTl_l, g_xTl_l);
    cudaGetSymbolAddress((void**)&wq_h,  g_Wq_h);  cudaGetSymbolAddress((void**)&wq_l,  g_Wq_l);
    cudaGetSymbolAddress((void**)&wk1_h, g_Wk1_h); cudaGetSymbolAddress((void**)&wk1_l, g_Wk1_l);
    cudaGetSymbolAddress((void**)&wk2_h, g_Wk2_h); cudaGetSymbolAddress((void**)&wk2_l, g_Wk2_l);
    cudaGetSymbolAddress((void**)&wv_h,  g_Wv_h);
    cudaGetSymbolAddress((void**)&q_h,  g_q_h);  cudaGetSymbolAddress((void**)&q_l,  g_q_l);
    cudaGetSymbolAddress((void**)&kf_h, g_kf_h); cudaGetSymbolAddress((void**)&kf_l, g_kf_l);
    cudaGetSymbolAddress((void**)&kl_h, g_kl_h); cudaGetSymbolAddress((void**)&kl_l, g_kl_l);
    cudaGetSymbolAddress((void**)&vT_h, g_vT_h);
    cudaGetSymbolAddress((void**)&s_h,  g_S_h);  cudaGetSymbolAddress((void**)&s_l,  g_S_l);
    cudaGetSymbolAddress((void**)&lf, g_lf);     cudaGetSymbolAddress((void**)&ll, g_ll);

    cudaFuncSetAttribute(mma_gemm, cudaFuncAttributeMaxDynamicSharedMemorySize, GEMM_SMEM);

    // 1) weight splits (one launch)
    {
        SJobs S = {};
        S.x[0] = Wq;  S.h[0] = wq_h;  S.l[0] = wq_l;
        S.x[1] = Wk1; S.h[1] = wk1_h; S.l[1] = wk1_l;
        S.x[2] = Wk2; S.h[2] = wk2_h; S.l[2] = wk2_l;
        S.x[3] = Wv;  S.h[3] = wv_h;  S.l[3] = nullptr;   // Wv lo unused
        int n0 = C_HALF * C_FULL;
        S.end[0] = n0; S.end[1] = 2 * n0; S.end[2] = 3 * n0;
        S.end[3] = 3 * n0 + C_FULL * C_FULL;
        split4_kernel<<<(S.end[3] + 255) / 256, 256>>>(S);
    }

    // 2) activation transposes + splits (one launch, z=3)
    {
        TJobs T = {};
        T.x[0] = x_m; T.th[0] = xTm_h; T.tl[0] = xTm_l;
        T.x[1] = x_f; T.th[1] = xTf_h; T.tl[1] = xTf_l;
        T.x[2] = x_l; T.th[2] = xTl_h; T.tl[2] = xTl_l;
        transpose_split<<<dim3(HW / 32, C_FULL / 32, 3), 256>>>(T);
    }

    // 3) all 4 conv GEMMs in ONE launch (640 CTAs)
    {
        Jobs P = {};
        const __half* Ahs[3] = {wq_h, wk1_h, wk2_h};
        const __half* Als[3] = {wq_l, wk1_l, wk2_l};
        const __half* Bhs[3] = {xTm_h, xTf_h, xTl_h};
        const __half* Bls[3] = {xTm_l, xTf_l, xTl_l};
        __half* Chs[3] = {q_h, kf_h, kl_h};
        __half* Cls[3] = {q_l, kf_l, kl_l};
        const float* bs[3] = {bq, bk1, bk2};
        for (int t = 0; t < 3; t++) {
            P.Ah[t] = Ahs[t]; P.Al[t] = Als[t]; P.Bh[t] = Bhs[t]; P.Bl[t] = Bls[t];
            P.Ch[t] = Chs[t]; P.Cl[t] = Cls[t]; P.bias[t] = bs[t];
            P.N[t] = HW; P.K[t] = C_FULL; P.gx[t] = HW / BN;
            P.tm[t] = 3; P.mode[t] = 0; P.blk0[t] = t * 128;
        }
        // job 3: vT = xT_m @ Wv^T + bv[n]
        P.Ah[3] = xTm_h; P.Al[3] = xTm_l; P.Bh[3] = wv_h; P.Bl[3] = nullptr;
        P.Ch[3] = vT_h; P.bias[3] = bv;
        P.N[3] = C_FULL; P.K[3] = C_FULL; P.gx[3] = C_FULL / BN;
        P.tm[3] = 2; P.mode[3] = 1; P.blk0[3] = 384;
        P.njobs = 4;
        mma_gemm<<<640, 256, GEMM_SMEM>>>(P);
    }

    // 4) logits (one launch, 128 CTAs)
    {
        Jobs P = {};
        P.Ah[0] = kf_h; P.Al[0] = kf_l; P.Bh[0] = q_h; P.Bl[0] = q_l; P.Cf[0] = lf;
        P.Ah[1] = kl_h; P.Al[1] = kl_l; P.Bh[1] = q_h; P.Bl[1] = q_l; P.Cf[1] = ll;
        for (int t = 0; t < 2; t++) {
            P.N[t] = C_FULL; P.K[t] = KLOG; P.gx[t] = C_FULL / BN;
            P.tm[t] = 3; P.mode[t] = 2; P.blk0[t] = t * 64;
        }
        P.njobs = 2;
        mma_gemm<<<128, 256, GEMM_SMEM>>>(P);
    }

    // 5) S = softmax(lf) + softmax(ll)
    softmax_sum_kernel<<<C_FULL, 256>>>(lf, ll, s_h, s_l);

    // 6) out = gamma * (S @ vT^T) + 0.5*(x_f + x_l)   (tm=2: hh + S_l*V_h)
    {
        Jobs P = {};
        P.Ah[0] = s_h; P.Al[0] = s_l; P.Bh[0] = vT_h; P.Bl[0] = nullptr;
        P.Cf[0] = out; P.xf = x_f; P.xl = x_l; P.gpt = gamma;
        P.N[0] = HW; P.K[0] = C_FULL; P.gx[0] = HW / BN;
        P.tm[0] = 2; P.mode[0] = 3; P.blk0[0] = 0;
        P.njobs = 1;
        mma_gemm<<<256, 256, GEMM_SMEM>>>(P);
    }
}

// round 6
// speedup vs baseline: 1.1465x; 1.1465x over previous
#include <cuda_runtime.h>
#include <cuda_fp16.h>
#include <math.h>
#include <stdint.h>

#define C_FULL 1024
#define C_HALF 512
#define HW     4096
#define KLOG   2048

// ---------------- scratch (device globals; no runtime allocation) ----------
__device__ __half g_xTm_h[HW*C_FULL], g_xTm_l[HW*C_FULL];
__device__ __half g_xTf_h[HW*C_FULL], g_xTf_l[HW*C_FULL];
__device__ __half g_xTl_h[HW*C_FULL], g_xTl_l[HW*C_FULL];
__device__ __half g_Wq_h [C_HALF*C_FULL], g_Wq_l [C_HALF*C_FULL];
__device__ __half g_Wk1_h[C_HALF*C_FULL], g_Wk1_l[C_HALF*C_FULL];
__device__ __half g_Wk2_h[C_HALF*C_FULL], g_Wk2_l[C_HALF*C_FULL];
__device__ __half g_Wv_h [C_FULL*C_FULL];                 // lo of Wv unused
__device__ __half g_q_h [C_HALF*HW], g_q_l [C_HALF*HW];
__device__ __half g_kf_h[C_HALF*HW], g_kf_l[C_HALF*HW];
__device__ __half g_kl_h[C_HALF*HW], g_kl_l[C_HALF*HW];
__device__ __half g_vT_h[HW*C_FULL];                      // lo of V unused
__device__ float  g_lf[C_FULL*C_FULL], g_ll[C_FULL*C_FULL];
__device__ __half g_S_h[C_FULL*C_FULL], g_S_l[C_FULL*C_FULL];

// ---------------- helpers ---------------------------------------------------
__device__ __forceinline__ uint32_t smem_u32(const void* p) {
    uint32_t r;
    asm("{ .reg .u64 t; cvta.to.shared.u64 t, %1; cvt.u32.u64 %0, t; }"
        : "=r"(r) : "l"(p));
    return r;
}
__device__ __forceinline__ void cp_async16(uint32_t dst, const void* src) {
    asm volatile("cp.async.cg.shared.global [%0], [%1], 16;" :: "r"(dst), "l"(src));
}
__device__ __forceinline__ void cp_commit() { asm volatile("cp.async.commit_group;"); }

__device__ __forceinline__ void ldsm4(uint32_t addr, uint32_t& r0, uint32_t& r1,
                                      uint32_t& r2, uint32_t& r3) {
    asm volatile("ldmatrix.sync.aligned.m8n8.x4.shared.b16 {%0,%1,%2,%3}, [%4];"
                 : "=r"(r0), "=r"(r1), "=r"(r2), "=r"(r3) : "r"(addr));
}
__device__ __forceinline__ void hmma(float* d, const uint32_t* a, const uint32_t* b) {
    asm volatile("mma.sync.aligned.m16n8k16.row.col.f32.f16.f16.f32 "
                 "{%0,%1,%2,%3}, {%4,%5,%6,%7}, {%8,%9}, {%0,%1,%2,%3};"
                 : "+f"(d[0]), "+f"(d[1]), "+f"(d[2]), "+f"(d[3])
                 : "r"(a[0]), "r"(a[1]), "r"(a[2]), "r"(a[3]),
                   "r"(b[0]), "r"(b[1]));
}

// ---------------- unified multi-job GEMM ------------------------------------
// D = A[M,K] @ B[N,K]^T, fp16-split operands, fp32 accum.
// tm bit0: add A_h*B_l term; tm bit1: add A_l*B_h term (A_h*B_h always).
// mode 0: split-store D+bias[m] -> Ch/Cl        (convs q/kf/kl)
// mode 1: hi-store   D+bias[n] -> Ch            (conv vT)
// mode 2: fp32 store D -> Cf                    (logits)
// mode 3: fp32 store gamma*D + 0.5*(xf+xl)->Cf  (final)
struct Jobs {
    const __half* Ah[4]; const __half* Al[4];
    const __half* Bh[4]; const __half* Bl[4];
    __half* Ch[4]; __half* Cl[4]; float* Cf[4];
    const float* bias[4];
    const float* xf; const float* xl; const float* gpt;
    int N[4], K[4], gx[4], tm[4], mode[4], blk0[4];
    int njobs;
};

#define BM 128
#define BN 128
#define BK 64
#define NTHR 512
#define TSTRIDE 72                            // 64 halves + 8 pad
#define TILE_BYTES (128 * TSTRIDE * 2)        // 18432
#define STAGE_BYTES (4 * TILE_BYTES)          // 73728
#define GEMM_SMEM (3 * STAGE_BYTES)           // 221184

__global__ __launch_bounds__(NTHR, 1)
void mma_gemm(Jobs P)
{
    extern __shared__ __half sm[];
    // job resolution
    int j = 0;
    #pragma unroll
    for (int t = 1; t < 4; t++)
        if (t < P.njobs && (int)blockIdx.x >= P.blk0[t]) j = t;
    const int rel = blockIdx.x - P.blk0[j];
    const int bx = rel % P.gx[j], by = rel / P.gx[j];

    const __half* __restrict__ Ah = P.Ah[j];
    const __half* __restrict__ Al = P.Al[j];
    const __half* __restrict__ Bh = P.Bh[j];
    const __half* __restrict__ Bl = P.Bl[j];
    const int N = P.N[j], K = P.K[j], tm = P.tm[j], mode = P.mode[j];

    const int tid  = threadIdx.x;
    const int lane = tid & 31, wid = tid >> 5;
    const int warp_m = wid & 3, warp_n = wid >> 2;       // 4 x 4 warps, 32x32
    const int bm0 = by * BM, bn0 = bx * BN;
    const uint32_t su = smem_u32(sm);

    float acc[2][4][4];
    #pragma unroll
    for (int i = 0; i < 2; i++)
        #pragma unroll
        for (int q = 0; q < 4; q++)
            #pragma unroll
            for (int k = 0; k < 4; k++) acc[i][q][k] = 0.0f;

#define LOAD_STAGE(s, kt) do {                                                \
    const uint32_t sbase_ = su + (uint32_t)(s) * STAGE_BYTES;                 \
    const size_t acol_ = (size_t)(kt) * BK;                                   \
    _Pragma("unroll")                                                         \
    for (int it_ = 0; it_ < 2; it_++) {                                       \
        const int c_ = tid + it_ * NTHR;                                      \
        const int row_ = c_ >> 3;                                             \
        const int kc_ = (c_ & 7) * 8;                                         \
        const uint32_t off_ = (uint32_t)(row_ * TSTRIDE + kc_) * 2;           \
        const size_t ga_ = (size_t)(bm0 + row_) * K + acol_ + kc_;            \
        const size_t gb_ = (size_t)(bn0 + row_) * K + acol_ + kc_;            \
        cp_async16(sbase_ + 0 * TILE_BYTES + off_, Ah + ga_);                 \
        cp_async16(sbase_ + 2 * TILE_BYTES + off_, Bh + gb_);                 \
        if (tm & 2) cp_async16(sbase_ + 1 * TILE_BYTES + off_, Al + ga_);     \
        if (tm & 1) cp_async16(sbase_ + 3 * TILE_BYTES + off_, Bl + gb_);     \
    }                                                                         \
    cp_commit();                                                              \
} while (0)

    const int NT = K / BK;
    LOAD_STAGE(0, 0);
    LOAD_STAGE(1, 1);

    for (int kt = 0; kt < NT; kt++) {
        if (kt + 2 < NT) {
            LOAD_STAGE((kt + 2) % 3, kt + 2);
            asm volatile("cp.async.wait_group 2;" ::: "memory");
        } else if (kt + 1 < NT) {
            asm volatile("cp.async.wait_group 1;" ::: "memory");
        } else {
            asm volatile("cp.async.wait_group 0;" ::: "memory");
        }
        __syncthreads();

        const uint32_t sbase = su + (uint32_t)(kt % 3) * STAGE_BYTES;
        #pragma unroll
        for (int ks = 0; ks < 4; ks++) {
            uint32_t ah[2][4], al[2][4], bh[4][2], bl[4][2];
            #pragma unroll
            for (int i = 0; i < 2; i++) {
                const int r   = warp_m * 32 + i * 16 + (lane & 15);
                const int col = ks * 16 + (lane >> 4) * 8;
                const uint32_t ad = sbase + (uint32_t)(r * TSTRIDE + col) * 2;
                ldsm4(ad, ah[i][0], ah[i][1], ah[i][2], ah[i][3]);
                if (tm & 2)
                    ldsm4(ad + TILE_BYTES, al[i][0], al[i][1], al[i][2], al[i][3]);
            }
            #pragma unroll
            for (int p = 0; p < 2; p++) {
                const int g  = lane >> 3, i8 = lane & 7;
                const int n   = warp_n * 32 + p * 16 + ((g >> 1) << 3) + i8;
                const int col = ks * 16 + (g & 1) * 8;
                const uint32_t bd = sbase + 2 * TILE_BYTES +
                                    (uint32_t)(n * TSTRIDE + col) * 2;
                ldsm4(bd, bh[2*p][0], bh[2*p][1], bh[2*p+1][0], bh[2*p+1][1]);
                if (tm & 1)
                    ldsm4(bd + TILE_BYTES, bl[2*p][0], bl[2*p][1], bl[2*p+1][0], bl[2*p+1][1]);
            }
            #pragma unroll
            for (int i = 0; i < 2; i++)
                #pragma unroll
                for (int q = 0; q < 4; q++)
                    hmma(acc[i][q], ah[i], bh[q]);
            if (tm & 2) {
                #pragma unroll
                for (int i = 0; i < 2; i++)
                    #pragma unroll
                    for (int q = 0; q < 4; q++)
                        hmma(acc[i][q], al[i], bh[q]);
            }
            if (tm & 1) {
                #pragma unroll
                for (int i = 0; i < 2; i++)
                    #pragma unroll
                    for (int q = 0; q < 4; q++)
                        hmma(acc[i][q], ah[i], bl[q]);
            }
        }
        __syncthreads();
    }
#undef LOAD_STAGE

    // ---- epilogue ----
    const int tq = lane >> 2, tr = lane & 3;
    const float gam = (mode == 3) ? P.gpt[0] : 0.0f;
    #pragma unroll
    for (int i = 0; i < 2; i++) {
        #pragma unroll
        for (int h2 = 0; h2 < 2; h2++) {
            const int row = bm0 + warp_m * 32 + i * 16 + tq + h2 * 8;
            const float bm_ = (mode == 0) ? P.bias[j][row] : 0.0f;
            #pragma unroll
            for (int q = 0; q < 4; q++) {
                const int col = bn0 + warp_n * 32 + q * 8 + tr * 2;
                float v0 = acc[i][q][h2 * 2 + 0];
                float v1 = acc[i][q][h2 * 2 + 1];
                const size_t idx = (size_t)row * N + col;
                if (mode == 0) {
                    v0 += bm_; v1 += bm_;
                    const __half h0 = __float2half_rn(v0);
                    const __half h1 = __float2half_rn(v1);
                    *reinterpret_cast<__half2*>(P.Ch[j] + idx) = __halves2half2(h0, h1);
                    *reinterpret_cast<__half2*>(P.Cl[j] + idx) =
                        __halves2half2(__float2half_rn(v0 - __half2float(h0)),
                                       __float2half_rn(v1 - __half2float(h1)));
                } else if (mode == 1) {
                    v0 += P.bias[j][col]; v1 += P.bias[j][col + 1];
                    *reinterpret_cast<__half2*>(P.Ch[j] + idx) =
                        __halves2half2(__float2half_rn(v0), __float2half_rn(v1));
                } else if (mode == 2) {
                    *reinterpret_cast<float2*>(P.Cf[j] + idx) = make_float2(v0, v1);
                } else {
                    const float2 a2 = *reinterpret_cast<const float2*>(P.xf + idx);
                    const float2 b2 = *reinterpret_cast<const float2*>(P.xl + idx);
                    *reinterpret_cast<float2*>(P.Cf[j] + idx) =
                        make_float2(gam * v0 + 0.5f * (a2.x + b2.x),
                                    gam * v1 + 0.5f * (a2.y + b2.y));
                }
            }
        }
    }
}

// ---------------- batched transpose + fp16 split ----------------------------
struct TJobs { const float* x[3]; __half* th[3]; __half* tl[3]; };
__global__ __launch_bounds__(256)
void transpose_split(TJobs T)
{
    __shared__ float t[32][33];
    const int z = blockIdx.z;
    const float* __restrict__ x = T.x[z];
    __half* __restrict__ th = T.th[z];
    __half* __restrict__ tl = T.tl[z];
    const int tx = threadIdx.x & 31, ty = threadIdx.x >> 5;
    const int c0 = blockIdx.x * 32;
    const int r0 = blockIdx.y * 32;
    #pragma unroll
    for (int i = 0; i < 4; i++)
        t[ty + i * 8][tx] = x[(size_t)(r0 + ty + i * 8) * HW + c0 + tx];
    __syncthreads();
    #pragma unroll
    for (int i = 0; i < 4; i++) {
        const float v = t[tx][ty + i * 8];
        const size_t idx = (size_t)(c0 + ty + i * 8) * C_FULL + r0 + tx;
        const __half h = __float2half_rn(v);
        th[idx] = h;
        tl[idx] = __float2half_rn(v - __half2float(h));
    }
}

// ---------------- merged weight splits (lo optional) ------------------------
struct SJobs { const float* x[4]; __half* h[4]; __half* l[4]; int end[4]; };
__global__ __launch_bounds__(256)
void split4_kernel(SJobs S)
{
    int i = blockIdx.x * 256 + threadIdx.x;
    int j = 0;
    #pragma unroll
    for (int t = 1; t < 4; t++) if (i >= S.end[t - 1]) j = t;
    const int base = (j == 0) ? 0 : S.end[j - 1];
    if (i >= S.end[3]) return;
    const int k = i - base;
    const float v = S.x[j][k];
    const __half hh = __float2half_rn(v);
    S.h[j][k] = hh;
    if (S.l[j]) S.l[j][k] = __float2half_rn(v - __half2float(hh));
}

// ---------------- fused dual softmax, split-fp16 output ---------------------
__global__ __launch_bounds__(256)
void softmax_sum_kernel(const float* __restrict__ LF, const float* __restrict__ LL,
                        __half* __restrict__ Sh, __half* __restrict__ Sl)
{
    const int row = blockIdx.x;
    const int tid = threadIdx.x;
    __shared__ float red[256];

    const float* pf = LF + (size_t)row * 1024;
    const float* pl = LL + (size_t)row * 1024;

    float vf[4], vl[4];
    #pragma unroll
    for (int k = 0; k < 4; k++) { vf[k] = pf[tid + 256 * k]; vl[k] = pl[tid + 256 * k]; }

    float m = fmaxf(fmaxf(vf[0], vf[1]), fmaxf(vf[2], vf[3]));
    red[tid] = m; __syncthreads();
    for (int s = 128; s > 0; s >>= 1) { if (tid < s) red[tid] = fmaxf(red[tid], red[tid + s]); __syncthreads(); }
    const float Mf = red[0]; __syncthreads();

    float ef[4], sf = 0.0f;
    #pragma unroll
    for (int k = 0; k < 4; k++) { ef[k] = expf(vf[k] - Mf); sf += ef[k]; }
    red[tid] = sf; __syncthreads();
    for (int s = 128; s > 0; s >>= 1) { if (tid < s) red[tid] += red[tid + s]; __syncthreads(); }
    const float Sf = red[0]; __syncthreads();

    m = fmaxf(fmaxf(vl[0], vl[1]), fmaxf(vl[2], vl[3]));
    red[tid] = m; __syncthreads();
    for (int s = 128; s > 0; s >>= 1) { if (tid < s) red[tid] = fmaxf(red[tid], red[tid + s]); __syncthreads(); }
    const float Ml = red[0]; __syncthreads();

    float el[4], sl = 0.0f;
    #pragma unroll
    for (int k = 0; k < 4; k++) { el[k] = expf(vl[k] - Ml); sl += el[k]; }
    red[tid] = sl; __syncthreads();
    for (int s = 128; s > 0; s >>= 1) { if (tid < s) red[tid] += red[tid + s]; __syncthreads(); }
    const float Sl_ = red[0];

    const float invf = 1.0f / Sf, invl = 1.0f / Sl_;
    #pragma unroll
    for (int k = 0; k < 4; k++) {
        const float v = ef[k] * invf + el[k] * invl;
        const size_t idx = (size_t)row * 1024 + tid + 256 * k;
        const __half h = __float2half_rn(v);
        Sh[idx] = h;
        Sl[idx] = __float2half_rn(v - __half2float(h));
    }
}

// ---------------------------------------------------------------------------
extern "C" void kernel_launch(void* const* d_in, const int* in_sizes, int n_in,
                              void* d_out, int out_size)
{
    (void)in_sizes; (void)n_in; (void)out_size;
    const float* x_f   = (const float*)d_in[0];
    const float* x_m   = (const float*)d_in[1];
    const float* x_l   = (const float*)d_in[2];
    const float* Wq    = (const float*)d_in[3];
    const float* bq    = (const float*)d_in[4];
    const float* Wk1   = (const float*)d_in[5];
    const float* bk1   = (const float*)d_in[6];
    const float* Wk2   = (const float*)d_in[7];
    const float* bk2   = (const float*)d_in[8];
    const float* Wv    = (const float*)d_in[9];
    const float* bv    = (const float*)d_in[10];
    const float* gamma = (const float*)d_in[11];
    float* out = (float*)d_out;

    __half *xTm_h, *xTm_l, *xTf_h, *xTf_l, *xTl_h, *xTl_l;
    __half *wq_h, *wq_l, *wk1_h, *wk1_l, *wk2_h, *wk2_l, *wv_h;
    __half *q_h, *q_l, *kf_h, *kf_l, *kl_h, *kl_l, *vT_h, *s_h, *s_l;
    float *lf, *ll;
    cudaGetSymbolAddress((void**)&xTm_h, g_xTm_h); cudaGetSymbolAddress((void**)&xTm_l, g_xTm_l);
    cudaGetSymbolAddress((void**)&xTf_h, g_xTf_h); cudaGetSymbolAddress((void**)&xTf_l, g_xTf_l);
    cudaGetSymbolAddress((void**)&xTl_h, g_xTl_h); cudaGetSymbolAddress((void**)&xTl_l, g_xTl_l);
    cudaGetSymbolAddress((void**)&wq_h,  g_Wq_h);  cudaGetSymbolAddress((void**)&wq_l,  g_Wq_l);
    cudaGetSymbolAddress((void**)&wk1_h, g_Wk1_h); cudaGetSymbolAddress((void**)&wk1_l, g_Wk1_l);
    cudaGetSymbolAddress((void**)&wk2_h, g_Wk2_h); cudaGetSymbolAddress((void**)&wk2_l, g_Wk2_l);
    cudaGetSymbolAddress((void**)&wv_h,  g_Wv_h);
    cudaGetSymbolAddress((void**)&q_h,  g_q_h);  cudaGetSymbolAddress((void**)&q_l,  g_q_l);
    cudaGetSymbolAddress((void**)&kf_h, g_kf_h); cudaGetSymbolAddress((void**)&kf_l, g_kf_l);
    cudaGetSymbolAddress((void**)&kl_h, g_kl_h); cudaGetSymbolAddress((void**)&kl_l, g_kl_l);
    cudaGetSymbolAddress((void**)&vT_h, g_vT_h);
    cudaGetSymbolAddress((void**)&s_h,  g_S_h);  cudaGetSymbolAddress((void**)&s_l,  g_S_l);
    cudaGetSymbolAddress((void**)&lf, g_lf);     cudaGetSymbolAddress((void**)&ll, g_ll);

    cudaFuncSetAttribute(mma_gemm, cudaFuncAttributeMaxDynamicSharedMemorySize, GEMM_SMEM);

    // 1) weight splits (one launch)
    {
        SJobs S = {};
        S.x[0] = Wq;  S.h[0] = wq_h;  S.l[0] = wq_l;
        S.x[1] = Wk1; S.h[1] = wk1_h; S.l[1] = wk1_l;
        S.x[2] = Wk2; S.h[2] = wk2_h; S.l[2] = wk2_l;
        S.x[3] = Wv;  S.h[3] = wv_h;  S.l[3] = nullptr;   // Wv lo unused
        int n0 = C_HALF * C_FULL;
        S.end[0] = n0; S.end[1] = 2 * n0; S.end[2] = 3 * n0;
        S.end[3] = 3 * n0 + C_FULL * C_FULL;
        split4_kernel<<<(S.end[3] + 255) / 256, 256>>>(S);
    }

    // 2) activation transposes + splits (one launch, z=3)
    {
        TJobs T = {};
        T.x[0] = x_m; T.th[0] = xTm_h; T.tl[0] = xTm_l;
        T.x[1] = x_f; T.th[1] = xTf_h; T.tl[1] = xTf_l;
        T.x[2] = x_l; T.th[2] = xTl_h; T.tl[2] = xTl_l;
        transpose_split<<<dim3(HW / 32, C_FULL / 32, 3), 256>>>(T);
    }

    // 3) all 4 conv GEMMs in ONE launch (640 CTAs)
    {
        Jobs P = {};
        const __half* Ahs[3] = {wq_h, wk1_h, wk2_h};
        const __half* Als[3] = {wq_l, wk1_l, wk2_l};
        const __half* Bhs[3] = {xTm_h, xTf_h, xTl_h};
        const __half* Bls[3] = {xTm_l, xTf_l, xTl_l};
        __half* Chs[3] = {q_h, kf_h, kl_h};
        __half* Cls[3] = {q_l, kf_l, kl_l};
        const float* bs[3] = {bq, bk1, bk2};
        for (int t = 0; t < 3; t++) {
            P.Ah[t] = Ahs[t]; P.Al[t] = Als[t]; P.Bh[t] = Bhs[t]; P.Bl[t] = Bls[t];
            P.Ch[t] = Chs[t]; P.Cl[t] = Cls[t]; P.bias[t] = bs[t];
            P.N[t] = HW; P.K[t] = C_FULL; P.gx[t] = HW / BN;
            P.tm[t] = 3; P.mode[t] = 0; P.blk0[t] = t * 128;
        }
        // job 3: vT = xT_m @ Wv^T + bv[n]
        P.Ah[3] = xTm_h; P.Al[3] = xTm_l; P.Bh[3] = wv_h; P.Bl[3] = nullptr;
        P.Ch[3] = vT_h; P.bias[3] = bv;
        P.N[3] = C_FULL; P.K[3] = C_FULL; P.gx[3] = C_FULL / BN;
        P.tm[3] = 2; P.mode[3] = 1; P.blk0[3] = 384;
        P.njobs = 4;
        mma_gemm<<<640, NTHR, GEMM_SMEM>>>(P);
    }

    // 4) logits (one launch, 128 CTAs)
    {
        Jobs P = {};
        P.Ah[0] = kf_h; P.Al[0] = kf_l; P.Bh[0] = q_h; P.Bl[0] = q_l; P.Cf[0] = lf;
        P.Ah[1] = kl_h; P.Al[1] = kl_l; P.Bh[1] = q_h; P.Bl[1] = q_l; P.Cf[1] = ll;
        for (int t = 0; t < 2; t++) {
            P.N[t] = C_FULL; P.K[t] = KLOG; P.gx[t] = C_FULL / BN;
            P.tm[t] = 3; P.mode[t] = 2; P.blk0[t] = t * 64;
        }
        P.njobs = 2;
        mma_gemm<<<128, NTHR, GEMM_SMEM>>>(P);
    }

    // 5) S = softmax(lf) + softmax(ll)
    softmax_sum_kernel<<<C_FULL, 256>>>(lf, ll, s_h, s_l);

    // 6) out = gamma * (S @ vT^T) + 0.5*(x_f + x_l)   (tm=2: hh + S_l*V_h)
    {
        Jobs P = {};
        P.Ah[0] = s_h; P.Al[0] = s_l; P.Bh[0] = vT_h; P.Bl[0] = nullptr;
        P.Cf[0] = out; P.xf = x_f; P.xl = x_l; P.gpt = gamma;
        P.N[0] = HW; P.K[0] = C_FULL; P.gx[0] = HW / BN;
        P.tm[0] = 2; P.mode[0] = 3; P.blk0[0] = 0;
        P.njobs = 1;
        mma_gemm<<<256, NTHR, GEMM_SMEM>>>(P);
    }
}